// round 11
// baseline (speedup 1.0000x reference)
#include <cuda_runtime.h>

#define B_EX   16384
#define NEG    10
#define NVAL   (NEG + 1)      // 11 values per example (pos + 10 neg)
#define WARPS_PER_BLOCK 8
#define THREADS (WARPS_PER_BLOCK * 32)
#define EX_ITERS 2
#define NBLOCKS (B_EX / (WARPS_PER_BLOCK * EX_ITERS))   // 1024
#define TOT_WARPS (NBLOCKS * WARPS_PER_BLOCK)           // 8192

// Scratch (allocation-free __device__ globals per harness rules)
__device__ float        g_partials[NBLOCKS];
__device__ unsigned int g_count = 0;

__device__ __forceinline__ float log_sigmoid(float x) {
    return fminf(x, 0.0f) - log1pf(expf(-fabsf(x)));
}

__device__ __forceinline__ float dot4(float4 a, float4 b) {
    return a.x * b.x + a.y * b.y + a.z * b.z + a.w * b.w;
}

__global__ void __launch_bounds__(THREADS)
w2v_fused_kernel(const int*    __restrict__ input_word,
                 const int*    __restrict__ context_word,
                 const int*    __restrict__ noise_words,
                 const float4* __restrict__ W_in,
                 const float4* __restrict__ W_ctx,
                 float*        __restrict__ out)
{
    // Per-warp private transpose pad: [11][33] floats, stride 33 -> both the
    // lane-major write and the column-sum read are bank-conflict-free.
    __shared__ float sp[WARPS_PER_BLOCK][NVAL][33];   // 11.6 KB
    __shared__ float s_warp[WARPS_PER_BLOCK];
    __shared__ bool  s_is_last;

    const int lane    = threadIdx.x & 31;
    const int warp_in = threadIdx.x >> 5;
    const int wg      = blockIdx.x * WARPS_PER_BLOCK + warp_in;  // global warp

    // Prefetch BOTH iterations' indices up front (uniform loads, one latency
    // exposure for all 24 indices).
    int ci[EX_ITERS], xi[EX_ITERS], nidx[EX_ITERS][NEG];
#pragma unroll
    for (int it = 0; it < EX_ITERS; it++) {
        const int b = it * TOT_WARPS + wg;
        ci[it] = input_word[b];
        xi[it] = context_word[b];
#pragma unroll
        for (int k = 0; k < NEG; k++)
            nidx[it][k] = noise_words[b * NEG + k];
    }

    float v_acc = 0.0f;   // lane 0: accumulated loss over both examples

#pragma unroll
    for (int it = 0; it < EX_ITERS; it++) {
        // Row = 128 floats = 32 float4; lane l owns float4 #l of each row.
        float4 c = W_in [(size_t)ci[it] * 32 + lane];
        float4 x = W_ctx[(size_t)xi[it] * 32 + lane];
        float4 nv[NEG];
#pragma unroll
        for (int k = 0; k < NEG; k++)
            nv[k] = W_ctx[(size_t)nidx[it][k] * 32 + lane];

        // Per-lane partial dots -> this warp's private smem pad.
        sp[warp_in][0][lane] = dot4(c, x);
#pragma unroll
        for (int k = 0; k < NEG; k++)
            sp[warp_in][1 + k][lane] = dot4(c, nv[k]);
        __syncwarp();     // warp-local only: no cross-warp coupling

        // Lanes 0..10: fixed-order column sum + log-sigmoid term.
        float term = 0.0f;
        if (lane < NVAL) {
            float s = 0.0f;
#pragma unroll
            for (int j = 0; j < 32; j++)
                s += sp[warp_in][lane][j];
            term = (lane == 0) ? -log_sigmoid(s) : -log_sigmoid(-s);
        }
        __syncwarp();

        // Butterfly over all 32 lanes (lanes >= 11 contribute 0): deterministic.
#pragma unroll
        for (int off = 16; off > 0; off >>= 1)
            term += __shfl_xor_sync(0xffffffffu, term, off);
        v_acc += term;    // identical value in all lanes; lane 0's is used
    }

    if (lane == 0) s_warp[warp_in] = v_acc;
    __syncthreads();      // single block barrier in the whole kernel

    if (threadIdx.x == 0) {
        float t = 0.0f;
#pragma unroll
        for (int i = 0; i < WARPS_PER_BLOCK; i++) t += s_warp[i];
        g_partials[blockIdx.x] = t;
        unsigned int cnt;
        asm volatile("atom.release.gpu.global.add.u32 %0, [%1], 1;"
                     : "=r"(cnt) : "l"(&g_count) : "memory");
        s_is_last = (cnt == (unsigned int)(NBLOCKS - 1));
    }
    __syncthreads();

    // ---- fused finalize: last block reduces all block partials ----
    if (s_is_last) {
        asm volatile("fence.acquire.gpu;" ::: "memory");
        volatile float* gp = g_partials;
        float tacc = 0.0f;
#pragma unroll
        for (int j = 0; j < NBLOCKS / THREADS; j++)     // 4 iterations
            tacc += gp[threadIdx.x + j * THREADS];

        __shared__ float s_red[THREADS];
        s_red[threadIdx.x] = tacc;
        __syncthreads();
#pragma unroll
        for (int step = THREADS / 2; step > 0; step >>= 1) {
            if (threadIdx.x < step) s_red[threadIdx.x] += s_red[threadIdx.x + step];
            __syncthreads();
        }
        if (threadIdx.x == 0) {
            out[0]  = s_red[0] / (float)B_EX;
            g_count = 0;                   // reset for next graph replay
        }
    }
}

extern "C" void kernel_launch(void* const* d_in, const int* in_sizes, int n_in,
                              void* d_out, int out_size)
{
    const int*    input_word   = (const int*)   d_in[0];
    const int*    context_word = (const int*)   d_in[1];
    const int*    noise_words  = (const int*)   d_in[2];
    const float4* W_in         = (const float4*)d_in[3];
    const float4* W_ctx        = (const float4*)d_in[4];
    float* out = (float*)d_out;

    w2v_fused_kernel<<<NBLOCKS, THREADS>>>(input_word, context_word,
                                           noise_words, W_in, W_ctx, out);
}